// round 3
// baseline (speedup 1.0000x reference)
#include <cuda_runtime.h>
#include <math.h>

#define BATCH  2
#define SEQ    2048
#define DMODEL 1024
#define NHEAD  16
#define DK     64
#define MROWS  (BATCH*SEQ)   // 4096

// ---------------- scratch (device globals; no allocations allowed) ----------
__device__ float g_q[(size_t)MROWS * DMODEL];   // RoPE'd Q, layout [b*s][e], pre-scaled by 1/8 at attn load
__device__ float g_k[(size_t)MROWS * DMODEL];   // RoPE'd K
__device__ float g_v[(size_t)MROWS * DMODEL];   // V
__device__ float g_o[(size_t)MROWS * DMODEL];   // attention output [b*s][h*64+d]
__device__ float g_cos[SEQ * 32];
__device__ float g_sin[SEQ * 32];

// ---------------- RoPE table -------------------------------------------------
__global__ void rope_table_kernel(const int* __restrict__ pos) {
    int idx = blockIdx.x * blockDim.x + threadIdx.x;
    if (idx >= SEQ * 32) return;
    int sp = idx >> 5;
    int i  = idx & 31;
    float p   = (float)pos[sp];
    // inv_freq = 1 / theta^{(2i)/dk} = 10000^{-i/32}
    float inv = powf(10000.0f, -((float)i) / 32.0f);
    float phi = p * inv;
    g_cos[idx] = cosf(phi);
    g_sin[idx] = sinf(phi);
}

// ---------------- SGEMM core: C[m,n] = sum_k A[m,k]*W[n,k]  (NT) -------------
// BM=128, BN=64, BK=16, 256 threads, 8x4 microtile per thread.
__device__ __forceinline__ void gemm_tile_128x64(
    const float* __restrict__ A, const float* __restrict__ W,
    float* __restrict__ C, bool rope)
{
    __shared__ float As[16][132];   // [k][m], padded
    __shared__ float Bs[16][68];    // [k][n], padded

    const int tid = threadIdx.x;
    const int bm0 = blockIdx.y * 128;
    const int bn0 = blockIdx.x * 64;
    const int tm = tid >> 4, tn = tid & 15;
    const int m0 = tm * 8,  n0 = tn * 4;

    float acc[8][4];
#pragma unroll
    for (int r = 0; r < 8; r++) {
        acc[r][0] = 0.f; acc[r][1] = 0.f; acc[r][2] = 0.f; acc[r][3] = 0.f;
    }

    for (int kb = 0; kb < DMODEL; kb += 16) {
        // load A tile: 128x16 = 512 float4, 2 per thread
#pragma unroll
        for (int t = 0; t < 2; t++) {
            int f  = tid + t * 256;
            int m  = f >> 2;
            int k4 = (f & 3) << 2;
            const float4 av = *(const float4*)(A + (size_t)(bm0 + m) * DMODEL + kb + k4);
            As[k4 + 0][m] = av.x; As[k4 + 1][m] = av.y;
            As[k4 + 2][m] = av.z; As[k4 + 3][m] = av.w;
        }
        // load W tile: 64x16 = 256 float4, 1 per thread
        {
            int n  = tid >> 2;
            int k4 = (tid & 3) << 2;
            const float4 bv = *(const float4*)(W + (size_t)(bn0 + n) * DMODEL + kb + k4);
            Bs[k4 + 0][n] = bv.x; Bs[k4 + 1][n] = bv.y;
            Bs[k4 + 2][n] = bv.z; Bs[k4 + 3][n] = bv.w;
        }
        __syncthreads();

#pragma unroll
        for (int kk = 0; kk < 16; kk++) {
            float4 a0 = *(const float4*)(&As[kk][m0]);
            float4 a1 = *(const float4*)(&As[kk][m0 + 4]);
            float4 bb = *(const float4*)(&Bs[kk][n0]);
            float ar[8] = {a0.x, a0.y, a0.z, a0.w, a1.x, a1.y, a1.z, a1.w};
#pragma unroll
            for (int r = 0; r < 8; r++) {
                acc[r][0] += ar[r] * bb.x;
                acc[r][1] += ar[r] * bb.y;
                acc[r][2] += ar[r] * bb.z;
                acc[r][3] += ar[r] * bb.w;
            }
        }
        __syncthreads();
    }

    // epilogue (+ fused RoPE: 4 consecutive cols => 2 complete even/odd pairs,
    // always inside one head since n0 % 4 == 0 and head width 64)
#pragma unroll
    for (int r = 0; r < 8; r++) {
        int row = bm0 + m0 + r;
        int col = bn0 + n0;
        float4 o = make_float4(acc[r][0], acc[r][1], acc[r][2], acc[r][3]);
        if (rope) {
            int sp = row & (SEQ - 1);          // seq position (rows are b*SEQ+s)
            int i0 = (col & (DK - 1)) >> 1;    // pair index within head
            float c0 = g_cos[sp * 32 + i0],     s0 = g_sin[sp * 32 + i0];
            float c1 = g_cos[sp * 32 + i0 + 1], s1 = g_sin[sp * 32 + i0 + 1];
            float e0 = o.x * c0 - o.y * s0;
            float e1 = o.x * s0 + o.y * c0;
            float e2 = o.z * c1 - o.w * s1;
            float e3 = o.z * s1 + o.w * c1;
            o = make_float4(e0, e1, e2, e3);
        }
        *(float4*)(C + (size_t)row * DMODEL + col) = o;
    }
}

__global__ void __launch_bounds__(256) qkv_kernel(
    const float* __restrict__ X,
    const float* __restrict__ Wq, const float* __restrict__ Wk,
    const float* __restrict__ Wv)
{
    const float* W; float* C; bool rope;
    if (blockIdx.z == 0)      { W = Wq; C = g_q; rope = true;  }
    else if (blockIdx.z == 1) { W = Wk; C = g_k; rope = true;  }
    else                      { W = Wv; C = g_v; rope = false; }
    gemm_tile_128x64(X, W, C, rope);
}

__global__ void __launch_bounds__(256) oproj_kernel(
    const float* __restrict__ Wo, float* __restrict__ Out)
{
    gemm_tile_128x64(g_o, Wo, Out, false);
}

// ---------------- causal flash attention, fp32, 1 thread = 1 query row ------
// BM=64 q rows (64 threads), BN=32 keys/tile, dk=64.
__global__ void __launch_bounds__(64) attn_kernel() {
    const int tid = threadIdx.x;
    const int qt = blockIdx.x;       // q tile (64 rows)
    const int h  = blockIdx.y;
    const int b  = blockIdx.z;
    const int qg = qt * 64 + tid;    // this thread's global q position

    __shared__ float  Qs[64][65];        // q tile (pre-scaled by 1/8), padded
    __shared__ float4 buf4[512];         // 8KB union: K^T [d][j] (64x32) then V [j][d] (32x64)
    __shared__ float  Ps[64][33];        // per-row probabilities for PV phase
    float* buf = (float*)buf4;

    // load Q tile, scaled by exactly 0.125 (power of two: bit-identical products)
    const float* qbase = g_q + (size_t)(b * SEQ + qt * 64) * DMODEL + h * DK;
#pragma unroll
    for (int it = 0; it < 16; it++) {
        int f  = tid + it * 64;          // 0..1023 float4s? no: 64x64 floats = 1024 float4/4
        int r  = f >> 4;
        int c0 = (f & 15) << 2;
        float4 qv = *(const float4*)(qbase + (size_t)r * DMODEL + c0);
        Qs[r][c0 + 0] = qv.x * 0.125f;
        Qs[r][c0 + 1] = qv.y * 0.125f;
        Qs[r][c0 + 2] = qv.z * 0.125f;
        Qs[r][c0 + 3] = qv.w * 0.125f;
    }

    float m = -1e30f, l = 0.f;
    float oa[64];
#pragma unroll
    for (int d = 0; d < 64; d++) oa[d] = 0.f;

    const int ntiles = qt * 2 + 2;   // keys up to (qt*64+63) inclusive
    const int nfull  = qt * 2;       // tiles fully below diagonal (no mask needed)
    const float* kbase = g_k + (size_t)(b * SEQ) * DMODEL + h * DK;
    const float* vbase = g_v + (size_t)(b * SEQ) * DMODEL + h * DK;

    for (int kt = 0; kt < ntiles; kt++) {
        const int kg0 = kt * 32;
        __syncthreads();   // previous PV readers done before K overwrites buf

        // load K tile TRANSPOSED: buf[d][j], j = lane -> conflict-free STS
#pragma unroll
        for (int it = 0; it < 8; it++) {
            int f  = tid + it * 64;      // 0..511 float4s
            int j  = f & 31;
            int d0 = (f >> 5) << 2;
            float4 kv = *(const float4*)(kbase + (size_t)(kg0 + j) * DMODEL + d0);
            buf[(d0 + 0) * 32 + j] = kv.x;
            buf[(d0 + 1) * 32 + j] = kv.y;
            buf[(d0 + 2) * 32 + j] = kv.z;
            buf[(d0 + 3) * 32 + j] = kv.w;
        }
        __syncthreads();

        // S = q . k  (per-thread row; K reads are uniform => smem broadcast)
        float s[32];
#pragma unroll
        for (int j = 0; j < 32; j++) s[j] = 0.f;
#pragma unroll 8
        for (int d = 0; d < 64; d++) {
            float qd = Qs[tid][d];
            const float4* K4 = buf4 + d * 8;
#pragma unroll
            for (int j4 = 0; j4 < 8; j4++) {
                float4 kk = K4[j4];
                s[j4 * 4 + 0] += qd * kk.x;
                s[j4 * 4 + 1] += qd * kk.y;
                s[j4 * 4 + 2] += qd * kk.z;
                s[j4 * 4 + 3] += qd * kk.w;
            }
        }
        __syncthreads();   // everyone done reading K before V overwrites buf

        // load V tile: buf4[j][d/4], contiguous float4 stores
#pragma unroll
        for (int it = 0; it < 8; it++) {
            int f  = tid + it * 64;
            int j  = f >> 4;
            int d0 = (f & 15) << 2;
            float4 vv = *(const float4*)(vbase + (size_t)(kg0 + j) * DMODEL + d0);
            buf4[j * 16 + (d0 >> 2)] = vv;
        }

        // online softmax (pure registers, own row)
        if (kt >= nfull) {
#pragma unroll
            for (int j = 0; j < 32; j++)
                if (kg0 + j > qg) s[j] = -1e30f;
        }
        float mn = m;
#pragma unroll
        for (int j = 0; j < 32; j++) mn = fmaxf(mn, s[j]);
        float alpha = __expf(m - mn);
        m = mn;
        float ps = 0.f;
#pragma unroll
        for (int j = 0; j < 32; j++) {
            float p = __expf(s[j] - mn);
            Ps[tid][j] = p;              // stash in smem so PV j-loop can stay rolled
            ps += p;
        }
        l = l * alpha + ps;
#pragma unroll
        for (int d = 0; d < 64; d++) oa[d] *= alpha;

        __syncthreads();   // V tile visible

        // O += P * V   (V reads uniform => broadcast; P read conflict-free: bank=(tid+j)%32)
#pragma unroll 4
        for (int j = 0; j < 32; j++) {
            float pj = Ps[tid][j];
            const float4* V4 = buf4 + j * 16;
#pragma unroll
            for (int d4 = 0; d4 < 16; d4++) {
                float4 vv = V4[d4];
                oa[d4 * 4 + 0] += pj * vv.x;
                oa[d4 * 4 + 1] += pj * vv.y;
                oa[d4 * 4 + 2] += pj * vv.z;
                oa[d4 * 4 + 3] += pj * vv.w;
            }
        }
    }

    // normalize + store
    float inv = 1.f / l;
    float* obase = g_o + (size_t)(b * SEQ + qg) * DMODEL + h * DK;
#pragma unroll
    for (int d4 = 0; d4 < 16; d4++) {
        float4 ov = make_float4(oa[d4 * 4 + 0] * inv, oa[d4 * 4 + 1] * inv,
                                oa[d4 * 4 + 2] * inv, oa[d4 * 4 + 3] * inv);
        *(float4*)(obase + d4 * 4) = ov;
    }
}

// ---------------- launch -----------------------------------------------------
extern "C" void kernel_launch(void* const* d_in, const int* in_sizes, int n_in,
                              void* d_out, int out_size) {
    (void)in_sizes; (void)n_in; (void)out_size;
    const float* x   = (const float*)d_in[0];
    const float* Wq  = (const float*)d_in[1];
    const float* Wk  = (const float*)d_in[2];
    const float* Wv  = (const float*)d_in[3];
    const float* Wo  = (const float*)d_in[4];
    const int*   pos = (const int*)  d_in[5];

    rope_table_kernel<<<(SEQ * 32 + 255) / 256, 256>>>(pos);

    dim3 gq(DMODEL / 64, MROWS / 128, 3);
    qkv_kernel<<<gq, 256>>>(x, Wq, Wk, Wv);

    dim3 ga(SEQ / 64, NHEAD, BATCH);
    attn_kernel<<<ga, 64>>>();

    dim3 go(DMODEL / 64, MROWS / 128, 1);
    oproj_kernel<<<go, 256>>>(Wo, (float*)d_out);
}

// round 5
// speedup vs baseline: 1.0501x; 1.0501x over previous
#include <cuda_runtime.h>
#include <math.h>

#define BATCH  2
#define SEQ    2048
#define DMODEL 1024
#define NHEAD  16
#define DK     64
#define MROWS  (BATCH*SEQ)   // 4096

typedef unsigned long long ull;

// ---- packed fp32x2 helpers (sm_100+ PTX; ptxas never emits these from C++) --
__device__ __forceinline__ ull fma2(ull a, ull b, ull c) {
    ull d;
    asm("fma.rn.f32x2 %0, %1, %2, %3;" : "=l"(d) : "l"(a), "l"(b), "l"(c));
    return d;
}
__device__ __forceinline__ ull mul2(ull a, ull b) {
    ull d;
    asm("mul.rn.f32x2 %0, %1, %2;" : "=l"(d) : "l"(a), "l"(b));
    return d;
}
__device__ __forceinline__ ull dup2(float x) {
    ull d;
    asm("mov.b64 %0, {%1, %1};" : "=l"(d) : "f"(x));
    return d;
}
__device__ __forceinline__ float2 unpack2(ull v) {
    float lo, hi;
    asm("mov.b64 {%0, %1}, %2;" : "=f"(lo), "=f"(hi) : "l"(v));
    return make_float2(lo, hi);
}

// ---------------- scratch (device globals; no allocations allowed) ----------
__device__ float g_q[(size_t)MROWS * DMODEL];   // RoPE'd Q
__device__ float g_k[(size_t)MROWS * DMODEL];   // RoPE'd K
__device__ float g_v[(size_t)MROWS * DMODEL];   // V
__device__ float g_o[(size_t)MROWS * DMODEL];   // attention output
__device__ float g_cos[SEQ * 32];
__device__ float g_sin[SEQ * 32];

// ---------------- RoPE table -------------------------------------------------
__global__ void rope_table_kernel(const int* __restrict__ pos) {
    int idx = blockIdx.x * blockDim.x + threadIdx.x;
    if (idx >= SEQ * 32) return;
    int sp = idx >> 5;
    int i  = idx & 31;
    float p   = (float)pos[sp];
    float inv = powf(10000.0f, -((float)i) / 32.0f);
    float phi = p * inv;
    g_cos[idx] = cosf(phi);
    g_sin[idx] = sinf(phi);
}

// ---------------- SGEMM core: C[m,n] = sum_k A[m,k]*W[n,k]  (NT) -------------
// BM=128, BN=64, BK=16, 256 threads, 8x4 microtile, accumulators packed along M.
__device__ __forceinline__ void gemm_tile_128x64(
    const float* __restrict__ A, const float* __restrict__ W,
    float* __restrict__ C, bool rope)
{
    __shared__ float As[16][132];   // [k][m], padded (row = 528B, 16B-aligned)
    __shared__ float Bs[16][68];    // [k][n], padded (row = 272B, 16B-aligned)

    const int tid = threadIdx.x;
    const int bm0 = blockIdx.y * 128;
    const int bn0 = blockIdx.x * 64;
    const int tm = tid >> 4, tn = tid & 15;
    const int m0 = tm * 8,  n0 = tn * 4;

    // acc2[r2][c] packs rows (m0+2*r2, m0+2*r2+1) of column c
    ull acc2[4][4];
#pragma unroll
    for (int r = 0; r < 4; r++)
#pragma unroll
        for (int c = 0; c < 4; c++) acc2[r][c] = 0ull;   // two packed +0.0f

    for (int kb = 0; kb < DMODEL; kb += 16) {
#pragma unroll
        for (int t = 0; t < 2; t++) {
            int f  = tid + t * 256;
            int m  = f >> 2;
            int k4 = (f & 3) << 2;
            const float4 av = *(const float4*)(A + (size_t)(bm0 + m) * DMODEL + kb + k4);
            As[k4 + 0][m] = av.x; As[k4 + 1][m] = av.y;
            As[k4 + 2][m] = av.z; As[k4 + 3][m] = av.w;
        }
        {
            int n  = tid >> 2;
            int k4 = (tid & 3) << 2;
            const float4 bv = *(const float4*)(W + (size_t)(bn0 + n) * DMODEL + kb + k4);
            Bs[k4 + 0][n] = bv.x; Bs[k4 + 1][n] = bv.y;
            Bs[k4 + 2][n] = bv.z; Bs[k4 + 3][n] = bv.w;
        }
        __syncthreads();

#pragma unroll
        for (int kk = 0; kk < 16; kk++) {
            // A m-pairs are consecutive in smem -> load directly as 64-bit pairs
            const ulonglong2* ap = (const ulonglong2*)(&As[kk][m0]);
            ulonglong2 a01 = ap[0];     // packs (m0,m0+1) and (m0+2,m0+3)
            ulonglong2 a23 = ap[1];     // packs (m0+4,m0+5) and (m0+6,m0+7)
            float4 bb = *(const float4*)(&Bs[kk][n0]);
            ull b0 = dup2(bb.x), b1 = dup2(bb.y), b2 = dup2(bb.z), b3 = dup2(bb.w);
            ull a2[4] = {a01.x, a01.y, a23.x, a23.y};
#pragma unroll
            for (int r = 0; r < 4; r++) {
                acc2[r][0] = fma2(a2[r], b0, acc2[r][0]);
                acc2[r][1] = fma2(a2[r], b1, acc2[r][1]);
                acc2[r][2] = fma2(a2[r], b2, acc2[r][2]);
                acc2[r][3] = fma2(a2[r], b3, acc2[r][3]);
            }
        }
        __syncthreads();
    }

    // unpack to scalar microtile
    float acc[8][4];
#pragma unroll
    for (int r = 0; r < 4; r++)
#pragma unroll
        for (int c = 0; c < 4; c++) {
            float2 u = unpack2(acc2[r][c]);
            acc[2 * r + 0][c] = u.x;
            acc[2 * r + 1][c] = u.y;
        }

    // epilogue (+ fused RoPE)
#pragma unroll
    for (int r = 0; r < 8; r++) {
        int row = bm0 + m0 + r;
        int col = bn0 + n0;
        float4 o = make_float4(acc[r][0], acc[r][1], acc[r][2], acc[r][3]);
        if (rope) {
            int sp = row & (SEQ - 1);
            int i0 = (col & (DK - 1)) >> 1;
            float c0 = g_cos[sp * 32 + i0],     s0 = g_sin[sp * 32 + i0];
            float c1 = g_cos[sp * 32 + i0 + 1], s1 = g_sin[sp * 32 + i0 + 1];
            float e0 = o.x * c0 - o.y * s0;
            float e1 = o.x * s0 + o.y * c0;
            float e2 = o.z * c1 - o.w * s1;
            float e3 = o.z * s1 + o.w * c1;
            o = make_float4(e0, e1, e2, e3);
        }
        *(float4*)(C + (size_t)row * DMODEL + col) = o;
    }
}

__global__ void __launch_bounds__(256) qkv_kernel(
    const float* __restrict__ X,
    const float* __restrict__ Wq, const float* __restrict__ Wk,
    const float* __restrict__ Wv)
{
    const float* W; float* C; bool rope;
    if (blockIdx.z == 0)      { W = Wq; C = g_q; rope = true;  }
    else if (blockIdx.z == 1) { W = Wk; C = g_k; rope = true;  }
    else                      { W = Wv; C = g_v; rope = false; }
    gemm_tile_128x64(X, W, C, rope);
}

__global__ void __launch_bounds__(256) oproj_kernel(
    const float* __restrict__ Wo, float* __restrict__ Out)
{
    gemm_tile_128x64(g_o, Wo, Out, false);
}

// ---------------- causal flash attention, fp32x2, 1 thread = 1 query row ----
__global__ void __launch_bounds__(64) attn_kernel() {
    const int tid = threadIdx.x;
    const int qt = blockIdx.x;
    const int h  = blockIdx.y;
    const int b  = blockIdx.z;
    const int qg = qt * 64 + tid;

    __shared__ float  Qs[64][65];
    __shared__ float4 buf4[512];         // union: K^T [d][j] (64x32) then V [j][d] (32x64)
    __shared__ float  Ps[64][33];
    float* buf = (float*)buf4;

    const float* qbase = g_q + (size_t)(b * SEQ + qt * 64) * DMODEL + h * DK;
#pragma unroll
    for (int it = 0; it < 16; it++) {
        int f  = tid + it * 64;
        int r  = f >> 4;
        int c0 = (f & 15) << 2;
        float4 qv = *(const float4*)(qbase + (size_t)r * DMODEL + c0);
        Qs[r][c0 + 0] = qv.x * 0.125f;
        Qs[r][c0 + 1] = qv.y * 0.125f;
        Qs[r][c0 + 2] = qv.z * 0.125f;
        Qs[r][c0 + 3] = qv.w * 0.125f;
    }

    float m = -1e30f, l = 0.f;
    ull o2[32];                         // packed O accumulator: o2[u] = pairs (2u, 2u+1)
#pragma unroll
    for (int d = 0; d < 32; d++) o2[d] = 0ull;

    const int ntiles = qt * 2 + 2;
    const int nfull  = qt * 2;
    const float* kbase = g_k + (size_t)(b * SEQ) * DMODEL + h * DK;
    const float* vbase = g_v + (size_t)(b * SEQ) * DMODEL + h * DK;

    for (int kt = 0; kt < ntiles; kt++) {
        const int kg0 = kt * 32;
        __syncthreads();

        // K tile transposed: buf[d][j], conflict-free STS (j = lane)
#pragma unroll
        for (int it = 0; it < 8; it++) {
            int f  = tid + it * 64;
            int j  = f & 31;
            int d0 = (f >> 5) << 2;
            float4 kv = *(const float4*)(kbase + (size_t)(kg0 + j) * DMODEL + d0);
            buf[(d0 + 0) * 32 + j] = kv.x;
            buf[(d0 + 1) * 32 + j] = kv.y;
            buf[(d0 + 2) * 32 + j] = kv.z;
            buf[(d0 + 3) * 32 + j] = kv.w;
        }
        __syncthreads();

        // S = q . k   (packed along j; K^T rows have j consecutive)
        // K2[j4].x packs scores (4*j4, 4*j4+1) -> s2[2*j4]; .y -> s2[2*j4+1]
        ull s2[16];
#pragma unroll
        for (int j = 0; j < 16; j++) s2[j] = 0ull;
#pragma unroll 8
        for (int d = 0; d < 64; d++) {
            ull qd2 = dup2(Qs[tid][d]);
            const ulonglong2* K2 = (const ulonglong2*)(buf + d * 32);
#pragma unroll
            for (int j4 = 0; j4 < 8; j4++) {
                ulonglong2 kk = K2[j4];
                s2[j4 * 2 + 0] = fma2(qd2, kk.x, s2[j4 * 2 + 0]);
                s2[j4 * 2 + 1] = fma2(qd2, kk.y, s2[j4 * 2 + 1]);
            }
        }
        __syncthreads();   // K readers done before V overwrites buf

        // V tile: buf4[j][d/4]
#pragma unroll
        for (int it = 0; it < 8; it++) {
            int f  = tid + it * 64;
            int j  = f >> 4;
            int d0 = (f & 15) << 2;
            float4 vv = *(const float4*)(vbase + (size_t)(kg0 + j) * DMODEL + d0);
            buf4[j * 16 + (d0 >> 2)] = vv;
        }

        // unpack scores, online softmax (scalar; own row)
        float s[32];
#pragma unroll
        for (int j = 0; j < 16; j++) {
            float2 u = unpack2(s2[j]);
            s[2 * j + 0] = u.x;
            s[2 * j + 1] = u.y;
        }
        if (kt >= nfull) {
#pragma unroll
            for (int j = 0; j < 32; j++)
                if (kg0 + j > qg) s[j] = -1e30f;
        }
        float mn = m;
#pragma unroll
        for (int j = 0; j < 32; j++) mn = fmaxf(mn, s[j]);
        float alpha = __expf(m - mn);
        m = mn;
        float ps = 0.f;
#pragma unroll
        for (int j = 0; j < 32; j++) {
            float p = __expf(s[j] - mn);
            Ps[tid][j] = p;
            ps += p;
        }
        l = l * alpha + ps;
        ull alpha2 = dup2(alpha);
#pragma unroll
        for (int d = 0; d < 32; d++) o2[d] = mul2(alpha2, o2[d]);

        __syncthreads();   // V tile visible

        // O += P * V   (packed along d; V row = 64 floats = 16 ulonglong2)
        // FIX vs R4: V2[u] covers floats 4u..4u+3; .x -> o2[2u], .y -> o2[2u+1]
#pragma unroll 4
        for (int j = 0; j < 32; j++) {
            ull pj2 = dup2(Ps[tid][j]);
            const ulonglong2* V2 = (const ulonglong2*)(buf4 + j * 16);
#pragma unroll
            for (int u = 0; u < 16; u++) {
                ulonglong2 vv = V2[u];
                o2[2 * u + 0] = fma2(pj2, vv.x, o2[2 * u + 0]);
                o2[2 * u + 1] = fma2(pj2, vv.y, o2[2 * u + 1]);
            }
        }
    }

    // normalize + store
    ull inv2 = dup2(1.f / l);
    float* obase = g_o + (size_t)(b * SEQ + qg) * DMODEL + h * DK;
#pragma unroll
    for (int d4 = 0; d4 < 16; d4++) {
        float2 u0 = unpack2(mul2(inv2, o2[d4 * 2 + 0]));
        float2 u1 = unpack2(mul2(inv2, o2[d4 * 2 + 1]));
        *(float4*)(obase + d4 * 4) = make_float4(u0.x, u0.y, u1.x, u1.y);
    }
}

// ---------------- launch -----------------------------------------------------
extern "C" void kernel_launch(void* const* d_in, const int* in_sizes, int n_in,
                              void* d_out, int out_size) {
    (void)in_sizes; (void)n_in; (void)out_size;
    const float* x   = (const float*)d_in[0];
    const float* Wq  = (const float*)d_in[1];
    const float* Wk  = (const float*)d_in[2];
    const float* Wv  = (const float*)d_in[3];
    const float* Wo  = (const float*)d_in[4];
    const int*   pos = (const int*)  d_in[5];

    rope_table_kernel<<<(SEQ * 32 + 255) / 256, 256>>>(pos);

    dim3 gq(DMODEL / 64, MROWS / 128, 3);
    qkv_kernel<<<gq, 256>>>(x, Wq, Wk, Wv);

    dim3 ga(SEQ / 64, NHEAD, BATCH);
    attn_kernel<<<ga, 64>>>();

    dim3 go(DMODEL / 64, MROWS / 128, 1);
    oproj_kernel<<<go, 256>>>(Wo, (float*)d_out);
}